// round 13
// baseline (speedup 1.0000x reference)
#include <cuda_runtime.h>
#include <math.h>

#define DEVF __device__ __forceinline__

// ---------------- problem constants ----------------
constexpr int HH = 512, WW = 512, NPIX = HH * WW, NC = 4;
constexpr int DBI = 5, DSP = 2;
constexpr int N_ITER = 10;

constexpr int BI_CAP = 1 << 22;
constexpr int SP_CAP = 1 << 19;
constexpr int BI_MMAX = NPIX * (DBI + 1); // 1,572,864
constexpr int SP_MMAX = NPIX * (DSP + 1); //   786,432
constexpr int BI_PAIRS = BI_MMAX / 2;
constexpr int SP_PAIRS = SP_MMAX / 2;
constexpr int NBKT = 16384;              // 128x128 grid of 4x4-pixel tiles
constexpr unsigned long long KEMPTY = ~0ull;
constexpr unsigned long long M40 = (1ull << 40) - 1;
constexpr float ALPHA_BI = 32.0f / 33.0f;
constexpr float ALPHA_SP = 0.8f;

// ---------------- device scratch ----------------
__device__ unsigned long long g_bi_hk[BI_CAP];   // key (40b) | id<<40 after assign
__device__ unsigned long long g_sp_hk[SP_CAP];
__device__ int   g_bi_bkt[BI_CAP];
__device__ int   g_sp_bkt[SP_CAP];
__device__ int   g_hist[2 * NBKT];
__device__ unsigned long long g_bi_kl[BI_MMAX];
__device__ unsigned long long g_sp_kl[SP_MMAX];
// interleaved (id, weight) pairs: .x = bitcast id (slot before fixoff), .y = barycentric w
__device__ __align__(16) float2 g_bi_ow[BI_MMAX];
__device__ __align__(16) float2 g_sp_ow[SP_MMAX];
__device__ __align__(16) int g_bi_bn[(DBI + 1) * BI_MMAX * 2];
__device__ __align__(16) int g_sp_bn[(DSP + 1) * SP_MMAX * 2];
// value buffers: A(0), B(1) ping-pong; C(2) = splat target
__device__ __align__(16) float g_bi_vA[BI_MMAX * NC];
__device__ __align__(16) float g_bi_vB[BI_MMAX * NC];
__device__ __align__(16) float g_bi_vC[BI_MMAX * NC];
__device__ __align__(16) float g_sp_vA[SP_MMAX * NC];
__device__ __align__(16) float g_sp_vB[SP_MMAX * NC];
__device__ __align__(16) float g_sp_vC[SP_MMAX * NC];
__device__ float g_bi_nA[BI_MMAX];
__device__ float g_bi_nB[BI_MMAX];
__device__ float g_sp_nA[SP_MMAX];
__device__ float g_sp_nB[SP_MMAX];
__device__ float g_bi_norm[NPIX];
__device__ float g_sp_norm[NPIX];
__device__ int   g_bi_cnt, g_sp_cnt;

// ---------------- templated accessors ----------------
template<int D> DEVF unsigned long long* HK()  { return D == DBI ? g_bi_hk  : g_sp_hk;  }
template<int D> DEVF int*    BKT() { return D == DBI ? g_bi_bkt : g_sp_bkt; }
template<int D> DEVF unsigned long long* KL()  { return D == DBI ? g_bi_kl  : g_sp_kl;  }
template<int D> DEVF float2* OWA() { return D == DBI ? g_bi_ow  : g_sp_ow;  }
template<int D> DEVF int*    BNA() { return D == DBI ? g_bi_bn  : g_sp_bn;  }
template<int D> DEVF int*    CNT() { return D == DBI ? &g_bi_cnt: &g_sp_cnt;}
template<int D> DEVF int     CAPC(){ return D == DBI ? BI_CAP   : SP_CAP;   }
template<int D> DEVF int     MMAXC(){ return D == DBI ? BI_MMAX : SP_MMAX;  }
template<int D> DEVF int     KBITS(){ return D == DBI ? 8 : 10; }
template<int D> DEVF int     KBIAS(){ return D == DBI ? 128 : 512; }
template<int D> DEVF unsigned KMASK(){ return D == DBI ? 0xFFu : 0x3FFu; }
template<int D> DEVF int     HBASE(){ return D == DBI ? 0 : NBKT; }

template<int D> DEVF float* VBUF(int which) {
    if (D == DBI) return which == 2 ? g_bi_vC : (which ? g_bi_vB : g_bi_vA);
    return which == 2 ? g_sp_vC : (which ? g_sp_vB : g_sp_vA);
}
template<int D> DEVF float* NBUF(int which) {
    return D == DBI ? (which ? g_bi_nB : g_bi_nA) : (which ? g_sp_nB : g_sp_nA);
}

// vectorized float4 reduction (sm_90+)
DEVF void red4(float* p, float a, float b, float c, float d) {
    asm volatile("{ .reg .u64 pg; cvta.to.global.u64 pg, %0; "
                 "red.global.add.v4.f32 [pg], {%1,%2,%3,%4}; }"
                 :: "l"(p), "f"(a), "f"(b), "f"(c), "f"(d) : "memory");
}
DEVF void red1(float* p, float a) {
    asm volatile("{ .reg .u64 pg; cvta.to.global.u64 pg, %0; "
                 "red.global.add.f32 [pg], %1; }"
                 :: "l"(p), "f"(a) : "memory");
}

// ---------------- hash ----------------
DEVF unsigned long long hmix(unsigned long long x) {
    x += 0x9E3779B97F4A7C15ull;
    x = (x ^ (x >> 30)) * 0xBF58476D1CE4E5B9ull;
    x = (x ^ (x >> 27)) * 0x94D049BB133111EBull;
    return x ^ (x >> 31);
}

template<int D>
DEVF int insert_slot(unsigned long long key, int bkt) {
    const unsigned mask = (unsigned)(CAPC<D>() - 1);
    unsigned long long* hk = HK<D>();
    unsigned h = (unsigned)hmix(key) & mask;
    for (;;) {
        unsigned long long prev = atomicCAS(&hk[h], KEMPTY, key);
        if (prev == KEMPTY) {
            BKT<D>()[h] = bkt;
            atomicAdd(&g_hist[HBASE<D>() + bkt], 1);
            return (int)h;
        }
        if (prev == key) return (int)h;
        h = (h + 1) & mask;
    }
}

template<int D>
DEVF int find_id(unsigned long long key) {
    const unsigned mask = (unsigned)(CAPC<D>() - 1);
    const unsigned long long* hk = HK<D>();
    unsigned h = (unsigned)hmix(key) & mask;
    for (;;) {
        unsigned long long v = hk[h];
        if (v == KEMPTY) return -1;
        if ((v & M40) == key) return (int)(v >> 40);
        h = (h + 1) & mask;
    }
}

// ---------------- setup kernels ----------------
// reset both hash tables + histograms in one launch
__global__ void k_resetAll() {
    int i = blockIdx.x * blockDim.x + threadIdx.x;
    if (i < BI_CAP) {
        g_bi_hk[i] = KEMPTY;
        if (i < 2 * NBKT) g_hist[i] = 0;
    } else {
        int k = i - BI_CAP;
        if (k < SP_CAP) g_sp_hk[k] = KEMPTY;
    }
}

template<int D>
__global__ void k_build(const float* __restrict__ x) {
    int n = blockIdx.x * blockDim.x + threadIdx.x;
    if (n >= NPIX) { cudaGridDependencySynchronize(); return; }
    int py = n / WW, px = n - py * WW;
    int bkt = ((py >> 2) << 7) | (px >> 2);   // 4x4 pixel tile id (128x128 grid)

    float fs[D];
    const double inv_std = sqrt(2.0 / 3.0) * (D + 1);
#pragma unroll
    for (int j = 0; j < D; j++) {
        float f;
        if (D == DBI) {
            if (j == 0)      f = __fdiv_rn((float)px, 80.0f);
            else if (j == 1) f = __fdiv_rn((float)py, 80.0f);
            else             f = __fdiv_rn(x[n * 7 + (6 - j)], 0.0625f);
        } else {
            f = __fdiv_rn((float)(j == 0 ? px : py), 3.0f);
        }
        float sc = (float)(1.0 / sqrt((j + 2.0) * (j + 1.0)) * inv_std);
        fs[j] = __fmul_rn(f, sc);
    }

    float elev[D + 1];
#pragma unroll
    for (int r = 0; r <= D; r++) {
        float s = 0.0f;
#pragma unroll
        for (int j = 0; j < D; j++) {
            float e = (r == 0) ? 1.0f : ((j == r - 1) ? -(float)r : (j >= r ? 1.0f : 0.0f));
            s = __fadd_rn(s, __fmul_rn(e, fs[j]));
        }
        elev[r] = s;
    }

    const float downf = __fdiv_rn(1.0f, (float)(D + 1));
    const float upf = (float)(D + 1);

    float rem0[D + 1], diff[D + 1];
    int   rnk[D + 1];
#pragma unroll
    for (int k = 0; k <= D; k++) {
        float v   = __fmul_rn(elev[k], downf);
        float upr = __fmul_rn(ceilf(v),  upf);
        float dnr = __fmul_rn(floorf(v), upf);
        rem0[k] = (__fsub_rn(upr, elev[k]) < __fsub_rn(elev[k], dnr)) ? upr : dnr;
    }
    float ssum = 0.0f;
#pragma unroll
    for (int k = 0; k <= D; k++) ssum = __fadd_rn(ssum, rem0[k]);
    int s = (int)__fmul_rn(ssum, downf);

#pragma unroll
    for (int k = 0; k <= D; k++) diff[k] = __fsub_rn(elev[k], rem0[k]);
#pragma unroll
    for (int k = 0; k <= D; k++) {
        int r = s;
#pragma unroll
        for (int j = 0; j <= D; j++) {
            if (j > k)      r += (diff[k] <  diff[j]);
            else if (j < k) r += (diff[j] >= diff[k]);
        }
        rnk[k] = r;
    }
#pragma unroll
    for (int k = 0; k <= D; k++) {
        if (rnk[k] < 0)      { rnk[k] += D + 1; rem0[k] = __fadd_rn(rem0[k], upf); }
        else if (rnk[k] > D) { rnk[k] -= D + 1; rem0[k] = __fsub_rn(rem0[k], upf); }
    }

    float b[D + 2];
#pragma unroll
    for (int k = 0; k < D + 2; k++) b[k] = 0.0f;
#pragma unroll
    for (int k = 0; k <= D; k++) {
        float vs = __fmul_rn(__fsub_rn(elev[k], rem0[k]), downf);
        int idx = D - rnk[k];
        b[idx]     = __fadd_rn(b[idx], vs);
        b[idx + 1] = __fsub_rn(b[idx + 1], vs);
    }
    b[0] = __fadd_rn(b[0], __fadd_rn(1.0f, b[D + 1]));

    int remi[D + 1];
#pragma unroll
    for (int k = 0; k <= D; k++) remi[k] = (int)rem0[k];

    // precompute all keys before touching the hash
    unsigned long long keys[D + 1];
#pragma unroll
    for (int m = 0; m <= D; m++) {
        unsigned long long key = 0ull;
#pragma unroll
        for (int j = 0; j < D; j++) {
            int r  = rnk[j];
            int cm = (r < D + 1 - m) ? m : m - (D + 1);
            int c  = remi[j] + cm;
            key |= ((unsigned long long)((unsigned)(c + KBIAS<D>()) & KMASK<D>())) << (KBITS<D>() * j);
        }
        keys[m] = key;
    }
    // wait for reset to finish before hash inserts
    cudaGridDependencySynchronize();
#pragma unroll
    for (int m = 0; m <= D; m++) {
        int slot = insert_slot<D>(keys[m], bkt);
        OWA<D>()[n * (D + 1) + m] = make_float2(__int_as_float(slot), b[m]);
    }
}

// exclusive scan of both 16384-entry histograms; 1024 threads x 16 elements
__global__ void k_scan() {
    cudaGridDependencySynchronize();
    __shared__ int sh[1024];
    int t = threadIdx.x;
#pragma unroll
    for (int half = 0; half < 2; half++) {
        int base = half * NBKT + t * 16;
        int v[16], lsum = 0;
#pragma unroll
        for (int e = 0; e < 16; e++) { v[e] = g_hist[base + e]; lsum += v[e]; }
        sh[t] = lsum;
        __syncthreads();
#pragma unroll
        for (int o = 1; o < 1024; o <<= 1) {
            int u = (t >= o) ? sh[t - o] : 0;
            __syncthreads();
            sh[t] += u;
            __syncthreads();
        }
        int run = sh[t] - lsum;   // exclusive base for this thread's 16 elements
#pragma unroll
        for (int e = 0; e < 16; e++) { g_hist[base + e] = run; run += v[e]; }
        if (t == 1023) {
            if (half == 0) g_bi_cnt = sh[1023];
            else           g_sp_cnt = sh[1023];
        }
        __syncthreads();
    }
}

__global__ void k_assign() {
    cudaGridDependencySynchronize();
    int i = blockIdx.x * blockDim.x + threadIdx.x;
    if (i < BI_CAP) {
        unsigned long long k = g_bi_hk[i];
        if (k != KEMPTY) {
            int id = atomicAdd(&g_hist[g_bi_bkt[i]], 1);
            g_bi_hk[i] = k | ((unsigned long long)id << 40);
            g_bi_kl[id] = k;
            g_bi_nA[id] = 0.0f;
            ((float4*)g_bi_vC)[id] = make_float4(0, 0, 0, 0);
        }
    } else {
        int j = i - BI_CAP;
        if (j < SP_CAP) {
            unsigned long long k = g_sp_hk[j];
            if (k != KEMPTY) {
                int id = atomicAdd(&g_hist[NBKT + g_sp_bkt[j]], 1);
                g_sp_hk[j] = k | ((unsigned long long)id << 40);
                g_sp_kl[id] = k;
                g_sp_nA[id] = 0.0f;
                ((float4*)g_sp_vC)[id] = make_float4(0, 0, 0, 0);
            }
        }
    }
}

__global__ void k_fixoff() {
    cudaGridDependencySynchronize();
    int i = blockIdx.x * blockDim.x + threadIdx.x;
    if (i < BI_MMAX) {
        int slot = __float_as_int(g_bi_ow[i].x);
        g_bi_ow[i].x = __int_as_float((int)(g_bi_hk[slot] >> 40));
    } else {
        int k = i - BI_MMAX;
        if (k < SP_MMAX) {
            int slot = __float_as_int(g_sp_ow[k].x);
            g_sp_ow[k].x = __int_as_float((int)(g_sp_hk[slot] >> 40));
        }
    }
}

template<int D>
DEVF void neigh_one(int i) {
    if (i >= *CNT<D>()) return;
    unsigned long long key = KL<D>()[i];
    int c[D];
#pragma unroll
    for (int j = 0; j < D; j++) c[j] = (int)((key >> (KBITS<D>() * j)) & KMASK<D>()) - KBIAS<D>();
#pragma unroll
    for (int j = 0; j <= D; j++) {
        unsigned long long k1 = 0ull, k2 = 0ull;
#pragma unroll
        for (int t = 0; t < D; t++) {
            int add = (j < D && t == j) ? (D + 1) : 0;
            int c1 = c[t] - 1 + add;
            int c2 = c[t] + 1 - add;
            k1 |= ((unsigned long long)((unsigned)(c1 + KBIAS<D>()) & KMASK<D>())) << (KBITS<D>() * t);
            k2 |= ((unsigned long long)((unsigned)(c2 + KBIAS<D>()) & KMASK<D>())) << (KBITS<D>() * t);
        }
        ((int2*)BNA<D>())[j * MMAXC<D>() + i] = make_int2(find_id<D>(k1), find_id<D>(k2));
    }
}

// both lattices in one launch
__global__ void k_neighAll() {
    cudaGridDependencySynchronize();
    int i = blockIdx.x * blockDim.x + threadIdx.x;
    if (i < BI_MMAX) neigh_one<DBI>(i);
    else { int k = i - BI_MMAX; if (k < SP_MMAX) neigh_one<DSP>(k); }
}

// ---------------- loop kernels (PDL-launched, implicit trigger at completion) ----------------

// initial Q = softmax(logits); splat Q into vC and ones into nA
__global__ void k_initQ(const float* __restrict__ logits) {
    int n = blockIdx.x * blockDim.x + threadIdx.x;
    if (n >= NPIX) { cudaGridDependencySynchronize(); return; }
    float4 lg = ((const float4*)logits)[n];
    cudaGridDependencySynchronize();   // ow/vC/nA ready (fixoff+assign complete)
    float2 bow[DBI + 1], sow[DSP + 1];
#pragma unroll
    for (int m = 0; m <= DBI; m++) bow[m] = g_bi_ow[n * (DBI + 1) + m];
#pragma unroll
    for (int m = 0; m <= DSP; m++) sow[m] = g_sp_ow[n * (DSP + 1) + m];
    float mx = fmaxf(fmaxf(lg.x, lg.y), fmaxf(lg.z, lg.w));
    float e0 = expf(lg.x - mx), e1 = expf(lg.y - mx), e2 = expf(lg.z - mx), e3 = expf(lg.w - mx);
    float inv = 1.0f / (e0 + e1 + e2 + e3);
    float q0 = e0 * inv, q1 = e1 * inv, q2 = e2 * inv, q3 = e3 * inv;
#pragma unroll
    for (int m = 0; m <= DBI; m++) {
        int id = __float_as_int(bow[m].x);
        float w = bow[m].y;
        red4(&g_bi_vC[id * 4], w * q0, w * q1, w * q2, w * q3);
        red1(&g_bi_nA[id], w);
    }
#pragma unroll
    for (int m = 0; m <= DSP; m++) {
        int id = __float_as_int(sow[m].x);
        float w = sow[m].y;
        red4(&g_sp_vC[id * 4], w * q0, w * q1, w * q2, w * q3);
        red1(&g_sp_nA[id], w);
    }
}

// value-blur of a pair (i, i+1); nbp preloaded
template<int D, int C, bool CLR>
DEVF void blur_vals(int i, int cnt, int4 nbp, int inb, int outb) {
    bool two = (i + 1 < cnt);
    {
        const float4* in = (const float4*)VBUF<D>(inb);
        float4* outp = (float4*)VBUF<D>(outb);
        float4 v0 = in[i];
        float4 a0 = make_float4(0, 0, 0, 0), b0 = a0;
        if (nbp.x >= 0) a0 = in[nbp.x];
        if (nbp.y >= 0) b0 = in[nbp.y];
        v0.x += 0.5f * (a0.x + b0.x); v0.y += 0.5f * (a0.y + b0.y);
        v0.z += 0.5f * (a0.z + b0.z); v0.w += 0.5f * (a0.w + b0.w);
        outp[i] = v0;
        if (two) {
            float4 v1 = in[i + 1];
            float4 a1 = make_float4(0, 0, 0, 0), b1 = a1;
            if (nbp.z >= 0) a1 = in[nbp.z];
            if (nbp.w >= 0) b1 = in[nbp.w];
            v1.x += 0.5f * (a1.x + b1.x); v1.y += 0.5f * (a1.y + b1.y);
            v1.z += 0.5f * (a1.z + b1.z); v1.w += 0.5f * (a1.w + b1.w);
            outp[i + 1] = v1;
        }
        if (CLR) {
            float4* cb = (float4*)VBUF<D>(2);
            cb[i] = make_float4(0, 0, 0, 0);
            if (two) cb[i + 1] = make_float4(0, 0, 0, 0);
        }
    }
    if (C == 5) {
        int nin = (inb == 2) ? 0 : inb;
        const float* in = NBUF<D>(nin);
        float* outp = NBUF<D>(outb);
        float s0 = 0.0f;
        if (nbp.x >= 0) s0 += in[nbp.x];
        if (nbp.y >= 0) s0 += in[nbp.y];
        outp[i] = in[i] + 0.5f * s0;
        if (two) {
            float s1 = 0.0f;
            if (nbp.z >= 0) s1 += in[nbp.z];
            if (nbp.w >= 0) s1 += in[nbp.w];
            outp[i + 1] = in[i + 1] + 0.5f * s1;
        }
    }
}

template<int C, bool CLR>
__global__ void k_blur(int axis, int inb, int outb) {
    int t = blockIdx.x * blockDim.x + threadIdx.x;
    // static prologue: counts + neighbor indices (written in setup, constant in loop)
    if (t < BI_PAIRS) {
        int i = 2 * t;
        int cnt = g_bi_cnt;
        if (i >= cnt) { cudaGridDependencySynchronize(); return; }
        int4 nbp = *(const int4*)(((const int2*)g_bi_bn) + axis * BI_MMAX + i);
        cudaGridDependencySynchronize();
        blur_vals<DBI, C, CLR>(i, cnt, nbp, inb, outb);
    } else {
        int k = t - BI_PAIRS;
        if (k >= SP_PAIRS) { cudaGridDependencySynchronize(); return; }
        int i = 2 * k;
        int cnt = g_sp_cnt;
        if (i >= cnt) { cudaGridDependencySynchronize(); return; }
        int4 nbp = *(const int4*)(((const int2*)g_sp_bn) + axis * SP_MMAX + i);
        cudaGridDependencySynchronize();
        blur_vals<DSP, C, CLR>(i, cnt, nbp, inb, outb);
    }
}

// mean-field update. MODE 0 = first (slices norm channel, stores norms),
// 1 = middle, 2 = last (writes output, no splat)
template<int MODE>
__global__ void k_update(const float* __restrict__ logits, float* __restrict__ out) {
    int n = blockIdx.x * blockDim.x + threadIdx.x;
    if (n >= NPIX) { cudaGridDependencySynchronize(); return; }
    // static prologue
    float2 bow[DBI + 1], sow[DSP + 1];
#pragma unroll
    for (int m = 0; m <= DBI; m++) bow[m] = g_bi_ow[n * (DBI + 1) + m];
#pragma unroll
    for (int m = 0; m <= DSP; m++) sow[m] = g_sp_ow[n * (DSP + 1) + m];
    float4 lg = ((const float4*)logits)[n];
    float nb_ = 0, ns_ = 0;
    if (MODE != 0) { nb_ = g_bi_norm[n]; ns_ = g_sp_norm[n]; }
    cudaGridDependencySynchronize();

    const float4* vb = (const float4*)g_bi_vA; // bi after 6 passes (C->B->A->B->A->B->A)
    const float4* vs = (const float4*)g_sp_vB; // sp after 3 passes (C->B->A->B)
    float ab0 = 0, ab1 = 0, ab2 = 0, ab3 = 0, sb = 0;
    float as0 = 0, as1 = 0, as2 = 0, as3 = 0, ss = 0;
#pragma unroll
    for (int m = 0; m <= DBI; m++) {
        int id = __float_as_int(bow[m].x);
        float w = bow[m].y;
        float4 t = vb[id];
        ab0 += w * t.x; ab1 += w * t.y; ab2 += w * t.z; ab3 += w * t.w;
        if (MODE == 0) sb += w * g_bi_nA[id];
    }
#pragma unroll
    for (int m = 0; m <= DSP; m++) {
        int id = __float_as_int(sow[m].x);
        float w = sow[m].y;
        float4 t = vs[id];
        as0 += w * t.x; as1 += w * t.y; as2 += w * t.z; as3 += w * t.w;
        if (MODE == 0) ss += w * g_sp_nB[id];
    }
    if (MODE == 0) {
        nb_ = sb * ALPHA_BI; g_bi_norm[n] = nb_;
        ns_ = ss * ALPHA_SP; g_sp_norm[n] = ns_;
    }
    float fbi = 10.0f * ALPHA_BI / (nb_ + 1e-20f);
    float fsp = 3.0f * ALPHA_SP / (ns_ + 1e-20f);
    float a0 = lg.x + fbi * ab0 + fsp * as0;
    float a1 = lg.y + fbi * ab1 + fsp * as1;
    float a2 = lg.z + fbi * ab2 + fsp * as2;
    float a3 = lg.w + fbi * ab3 + fsp * as3;
    float mx = fmaxf(fmaxf(a0, a1), fmaxf(a2, a3));
    float e0 = expf(a0 - mx), e1 = expf(a1 - mx), e2 = expf(a2 - mx), e3 = expf(a3 - mx);
    float inv = 1.0f / (e0 + e1 + e2 + e3);
    float q0 = e0 * inv, q1 = e1 * inv, q2 = e2 * inv, q3 = e3 * inv;
    if (MODE == 2) {
        ((float4*)out)[n] = make_float4(q0, q1, q2, q3);
    } else {
#pragma unroll
        for (int m = 0; m <= DBI; m++) {
            int id = __float_as_int(bow[m].x);
            float w = bow[m].y;
            red4(&g_bi_vC[id * 4], w * q0, w * q1, w * q2, w * q3);
        }
#pragma unroll
        for (int m = 0; m <= DSP; m++) {
            int id = __float_as_int(sow[m].x);
            float w = sow[m].y;
            red4(&g_sp_vC[id * 4], w * q0, w * q1, w * q2, w * q3);
        }
    }
}

// ---------------- launch ----------------
template<typename K, typename... Args>
static void launch_pdl(unsigned grid, unsigned block, K kernel, Args... args) {
    cudaLaunchConfig_t cfg = {};
    cfg.gridDim = dim3(grid, 1, 1);
    cfg.blockDim = dim3(block, 1, 1);
    cfg.dynamicSmemBytes = 0;
    cfg.stream = 0;
    cudaLaunchAttribute at[1];
    at[0].id = cudaLaunchAttributeProgrammaticStreamSerialization;
    at[0].val.programmaticStreamSerializationAllowed = 1;
    cfg.attrs = at;
    cfg.numAttrs = 1;
    cudaLaunchKernelEx(&cfg, kernel, args...);
}

extern "C" void kernel_launch(void* const* d_in, const int* in_sizes, int n_in,
                              void* d_out, int out_size) {
    (void)in_sizes; (void)n_in; (void)out_size;
    const float* x      = (const float*)d_in[0];
    const float* logits = (const float*)d_in[1];
    float* out = (float*)d_out;

    const int B = 256;
    auto g = [](long n) { return (unsigned)((n + 255) / 256); };
    const unsigned G_BOTH   = g(BI_MMAX + SP_MMAX);
    const unsigned G_CAPS   = g(BI_CAP + SP_CAP);
    const unsigned G_PAIRS  = g(BI_PAIRS + SP_PAIRS);
    const unsigned G_PAIRSB = g(BI_PAIRS);
    const unsigned G_PIX    = g(NPIX);

    // ---- lattice construction (PDL chain) ----
    k_resetAll<<<G_CAPS, B>>>();
    launch_pdl(G_PIX, B, k_build<DBI>, x);
    launch_pdl(G_PIX, B, k_build<DSP>, x);
    launch_pdl(1u, 1024u, k_scan);
    launch_pdl(G_CAPS, B, k_assign);
    launch_pdl(G_BOTH, B, k_fixoff);
    launch_pdl(G_BOTH, B, k_neighAll);

    // ---- init + mean-field iterations (PDL chain; norm fused into iteration 0) ----
    launch_pdl(G_PIX, B, k_initQ, logits);
    for (int it = 0; it < N_ITER; it++) {
        for (int j = 0; j <= DBI; j++) {
            int inb  = (j == 0) ? 2 : (j & 1);
            int outb = (j & 1) ^ 1;
            unsigned grd = (j <= DSP) ? G_PAIRS : G_PAIRSB;
            if (it == 0) {
                if (j == 1) launch_pdl(grd, B, k_blur<5, true>,  j, inb, outb);
                else        launch_pdl(grd, B, k_blur<5, false>, j, inb, outb);
            } else {
                if (j == 1) launch_pdl(grd, B, k_blur<4, true>,  j, inb, outb);
                else        launch_pdl(grd, B, k_blur<4, false>, j, inb, outb);
            }
        }
        if (it == 0)
            launch_pdl(G_PIX, B, k_update<0>, logits, out);
        else if (it == N_ITER - 1)
            launch_pdl(G_PIX, B, k_update<2>, logits, out);
        else
            launch_pdl(G_PIX, B, k_update<1>, logits, out);
    }
}

// round 16
// speedup vs baseline: 1.0060x; 1.0060x over previous
#include <cuda_runtime.h>
#include <math.h>

#define DEVF __device__ __forceinline__

// ---------------- problem constants ----------------
constexpr int HH = 512, WW = 512, NPIX = HH * WW, NC = 4;
constexpr int DBI = 5, DSP = 2;
constexpr int N_ITER = 10;

constexpr int BI_CAP = 1 << 22;
constexpr int SP_CAP = 1 << 19;
constexpr int BI_MMAX = NPIX * (DBI + 1); // 1,572,864
constexpr int SP_MMAX = NPIX * (DSP + 1); //   786,432
constexpr int BI_PAIRS = BI_MMAX / 2;
constexpr int SP_PAIRS = SP_MMAX / 2;
constexpr int NBKT = 16384;              // 128x128 grid of 4x4-pixel tiles
constexpr unsigned long long KEMPTY = ~0ull;
constexpr unsigned long long M40 = (1ull << 40) - 1;
constexpr float ALPHA_BI = 32.0f / 33.0f;
constexpr float ALPHA_SP = 0.8f;

// ---------------- device scratch ----------------
__device__ unsigned long long g_bi_hk[BI_CAP];   // key (40b) | id<<40 after assign
__device__ unsigned long long g_sp_hk[SP_CAP];
__device__ int   g_bi_bkt[BI_CAP];
__device__ int   g_sp_bkt[SP_CAP];
__device__ int   g_hist[2 * NBKT];
__device__ unsigned long long g_bi_kl[BI_MMAX];
__device__ unsigned long long g_sp_kl[SP_MMAX];
// interleaved (id, weight) pairs: .x = bitcast id (slot before fixoff), .y = barycentric w
__device__ __align__(16) float2 g_bi_ow[BI_MMAX];
__device__ __align__(16) float2 g_sp_ow[SP_MMAX];
__device__ __align__(16) int g_bi_bn[(DBI + 1) * BI_MMAX * 2];
__device__ __align__(16) int g_sp_bn[(DSP + 1) * SP_MMAX * 2];
// value buffers: A(0), B(1) ping-pong; C(2) = splat target
__device__ __align__(16) float g_bi_vA[BI_MMAX * NC];
__device__ __align__(16) float g_bi_vB[BI_MMAX * NC];
__device__ __align__(16) float g_bi_vC[BI_MMAX * NC];
__device__ __align__(16) float g_sp_vA[SP_MMAX * NC];
__device__ __align__(16) float g_sp_vB[SP_MMAX * NC];
__device__ __align__(16) float g_sp_vC[SP_MMAX * NC];
__device__ float g_bi_nA[BI_MMAX];
__device__ float g_bi_nB[BI_MMAX];
__device__ float g_sp_nA[SP_MMAX];
__device__ float g_sp_nB[SP_MMAX];
__device__ float g_bi_norm[NPIX];
__device__ float g_sp_norm[NPIX];
__device__ int   g_bi_cnt, g_sp_cnt;

// ---------------- templated accessors ----------------
template<int D> DEVF unsigned long long* HK()  { return D == DBI ? g_bi_hk  : g_sp_hk;  }
template<int D> DEVF int*    BKT() { return D == DBI ? g_bi_bkt : g_sp_bkt; }
template<int D> DEVF unsigned long long* KL()  { return D == DBI ? g_bi_kl  : g_sp_kl;  }
template<int D> DEVF float2* OWA() { return D == DBI ? g_bi_ow  : g_sp_ow;  }
template<int D> DEVF int*    BNA() { return D == DBI ? g_bi_bn  : g_sp_bn;  }
template<int D> DEVF int*    CNT() { return D == DBI ? &g_bi_cnt: &g_sp_cnt;}
template<int D> DEVF int     CAPC(){ return D == DBI ? BI_CAP   : SP_CAP;   }
template<int D> DEVF int     MMAXC(){ return D == DBI ? BI_MMAX : SP_MMAX;  }
template<int D> DEVF int     KBITS(){ return D == DBI ? 8 : 10; }
template<int D> DEVF int     KBIAS(){ return D == DBI ? 128 : 512; }
template<int D> DEVF unsigned KMASK(){ return D == DBI ? 0xFFu : 0x3FFu; }
template<int D> DEVF int     HBASE(){ return D == DBI ? 0 : NBKT; }

template<int D> DEVF float* VBUF(int which) {
    if (D == DBI) return which == 2 ? g_bi_vC : (which ? g_bi_vB : g_bi_vA);
    return which == 2 ? g_sp_vC : (which ? g_sp_vB : g_sp_vA);
}
template<int D> DEVF float* NBUF(int which) {
    return D == DBI ? (which ? g_bi_nB : g_bi_nA) : (which ? g_sp_nB : g_sp_nA);
}

// vectorized float4 reduction (sm_90+)
DEVF void red4(float* p, float a, float b, float c, float d) {
    asm volatile("{ .reg .u64 pg; cvta.to.global.u64 pg, %0; "
                 "red.global.add.v4.f32 [pg], {%1,%2,%3,%4}; }"
                 :: "l"(p), "f"(a), "f"(b), "f"(c), "f"(d) : "memory");
}
DEVF void red1(float* p, float a) {
    asm volatile("{ .reg .u64 pg; cvta.to.global.u64 pg, %0; "
                 "red.global.add.f32 [pg], %1; }"
                 :: "l"(p), "f"(a) : "memory");
}

// ---------------- hash ----------------
DEVF unsigned long long hmix(unsigned long long x) {
    x += 0x9E3779B97F4A7C15ull;
    x = (x ^ (x >> 30)) * 0xBF58476D1CE4E5B9ull;
    x = (x ^ (x >> 27)) * 0x94D049BB133111EBull;
    return x ^ (x >> 31);
}

template<int D>
DEVF int insert_slot(unsigned long long key, int bkt) {
    const unsigned mask = (unsigned)(CAPC<D>() - 1);
    unsigned long long* hk = HK<D>();
    unsigned h = (unsigned)hmix(key) & mask;
    for (;;) {
        unsigned long long prev = atomicCAS(&hk[h], KEMPTY, key);
        if (prev == KEMPTY) {
            BKT<D>()[h] = bkt;
            atomicAdd(&g_hist[HBASE<D>() + bkt], 1);
            return (int)h;
        }
        if (prev == key) return (int)h;
        h = (h + 1) & mask;
    }
}

template<int D>
DEVF int find_id(unsigned long long key) {
    const unsigned mask = (unsigned)(CAPC<D>() - 1);
    const unsigned long long* hk = HK<D>();
    unsigned h = (unsigned)hmix(key) & mask;
    for (;;) {
        unsigned long long v = hk[h];
        if (v == KEMPTY) return -1;
        if ((v & M40) == key) return (int)(v >> 40);
        h = (h + 1) & mask;
    }
}

// ---------------- setup kernels ----------------
// reset both hash tables + histograms in one launch
__global__ void k_resetAll() {
    int i = blockIdx.x * blockDim.x + threadIdx.x;
    if (i < BI_CAP) {
        g_bi_hk[i] = KEMPTY;
        if (i < 2 * NBKT) g_hist[i] = 0;
    } else {
        int k = i - BI_CAP;
        if (k < SP_CAP) g_sp_hk[k] = KEMPTY;
    }
}

template<int D>
__global__ void k_build(const float* __restrict__ x) {
    int n = blockIdx.x * blockDim.x + threadIdx.x;
    if (n >= NPIX) { cudaGridDependencySynchronize(); return; }
    int py = n / WW, px = n - py * WW;
    int bkt = ((py >> 2) << 7) | (px >> 2);   // 4x4 pixel tile id (128x128 grid)

    float fs[D];
    const double inv_std = sqrt(2.0 / 3.0) * (D + 1);
#pragma unroll
    for (int j = 0; j < D; j++) {
        float f;
        if (D == DBI) {
            if (j == 0)      f = __fdiv_rn((float)px, 80.0f);
            else if (j == 1) f = __fdiv_rn((float)py, 80.0f);
            else             f = __fdiv_rn(x[n * 7 + (6 - j)], 0.0625f);
        } else {
            f = __fdiv_rn((float)(j == 0 ? px : py), 3.0f);
        }
        float sc = (float)(1.0 / sqrt((j + 2.0) * (j + 1.0)) * inv_std);
        fs[j] = __fmul_rn(f, sc);
    }

    float elev[D + 1];
#pragma unroll
    for (int r = 0; r <= D; r++) {
        float s = 0.0f;
#pragma unroll
        for (int j = 0; j < D; j++) {
            float e = (r == 0) ? 1.0f : ((j == r - 1) ? -(float)r : (j >= r ? 1.0f : 0.0f));
            s = __fadd_rn(s, __fmul_rn(e, fs[j]));
        }
        elev[r] = s;
    }

    const float downf = __fdiv_rn(1.0f, (float)(D + 1));
    const float upf = (float)(D + 1);

    float rem0[D + 1], diff[D + 1];
    int   rnk[D + 1];
#pragma unroll
    for (int k = 0; k <= D; k++) {
        float v   = __fmul_rn(elev[k], downf);
        float upr = __fmul_rn(ceilf(v),  upf);
        float dnr = __fmul_rn(floorf(v), upf);
        rem0[k] = (__fsub_rn(upr, elev[k]) < __fsub_rn(elev[k], dnr)) ? upr : dnr;
    }
    float ssum = 0.0f;
#pragma unroll
    for (int k = 0; k <= D; k++) ssum = __fadd_rn(ssum, rem0[k]);
    int s = (int)__fmul_rn(ssum, downf);

#pragma unroll
    for (int k = 0; k <= D; k++) diff[k] = __fsub_rn(elev[k], rem0[k]);
#pragma unroll
    for (int k = 0; k <= D; k++) {
        int r = s;
#pragma unroll
        for (int j = 0; j <= D; j++) {
            if (j > k)      r += (diff[k] <  diff[j]);
            else if (j < k) r += (diff[j] >= diff[k]);
        }
        rnk[k] = r;
    }
#pragma unroll
    for (int k = 0; k <= D; k++) {
        if (rnk[k] < 0)      { rnk[k] += D + 1; rem0[k] = __fadd_rn(rem0[k], upf); }
        else if (rnk[k] > D) { rnk[k] -= D + 1; rem0[k] = __fsub_rn(rem0[k], upf); }
    }

    float b[D + 2];
#pragma unroll
    for (int k = 0; k < D + 2; k++) b[k] = 0.0f;
#pragma unroll
    for (int k = 0; k <= D; k++) {
        float vs = __fmul_rn(__fsub_rn(elev[k], rem0[k]), downf);
        int idx = D - rnk[k];
        b[idx]     = __fadd_rn(b[idx], vs);
        b[idx + 1] = __fsub_rn(b[idx + 1], vs);
    }
    b[0] = __fadd_rn(b[0], __fadd_rn(1.0f, b[D + 1]));

    int remi[D + 1];
#pragma unroll
    for (int k = 0; k <= D; k++) remi[k] = (int)rem0[k];

    // precompute all keys before touching the hash
    unsigned long long keys[D + 1];
#pragma unroll
    for (int m = 0; m <= D; m++) {
        unsigned long long key = 0ull;
#pragma unroll
        for (int j = 0; j < D; j++) {
            int r  = rnk[j];
            int cm = (r < D + 1 - m) ? m : m - (D + 1);
            int c  = remi[j] + cm;
            key |= ((unsigned long long)((unsigned)(c + KBIAS<D>()) & KMASK<D>())) << (KBITS<D>() * j);
        }
        keys[m] = key;
    }
    // wait for reset to finish before hash inserts
    cudaGridDependencySynchronize();
#pragma unroll
    for (int m = 0; m <= D; m++) {
        int slot = insert_slot<D>(keys[m], bkt);
        OWA<D>()[n * (D + 1) + m] = make_float2(__int_as_float(slot), b[m]);
    }
}

// exclusive scan of both 16384-entry histograms; warp-shuffle hierarchical scan
__global__ void k_scan() {
    cudaGridDependencySynchronize();
    __shared__ int warpsum[32];
    int t = threadIdx.x;
    int lane = t & 31, wid = t >> 5;
#pragma unroll
    for (int half = 0; half < 2; half++) {
        int base = half * NBKT + t * 16;
        int v[16], lsum = 0;
#pragma unroll
        for (int e = 0; e < 16; e++) { v[e] = g_hist[base + e]; lsum += v[e]; }
        // warp-inclusive scan of per-thread sums
        int inc = lsum;
#pragma unroll
        for (int o = 1; o < 32; o <<= 1) {
            int u = __shfl_up_sync(0xFFFFFFFFu, inc, o);
            if (lane >= o) inc += u;
        }
        if (lane == 31) warpsum[wid] = inc;
        __syncthreads();
        if (wid == 0) {
            int ws = warpsum[lane];
#pragma unroll
            for (int o = 1; o < 32; o <<= 1) {
                int u = __shfl_up_sync(0xFFFFFFFFu, ws, o);
                if (lane >= o) ws += u;
            }
            warpsum[lane] = ws;
        }
        __syncthreads();
        int excl = inc - lsum + (wid > 0 ? warpsum[wid - 1] : 0);
        int run = excl;
#pragma unroll
        for (int e = 0; e < 16; e++) { g_hist[base + e] = run; run += v[e]; }
        if (t == 0) {
            if (half == 0) g_bi_cnt = warpsum[31];
            else           g_sp_cnt = warpsum[31];
        }
        __syncthreads();   // protect warpsum reuse in next half
    }
}

__global__ void k_assign() {
    cudaGridDependencySynchronize();
    int i = blockIdx.x * blockDim.x + threadIdx.x;
    if (i < BI_CAP) {
        unsigned long long k = g_bi_hk[i];
        if (k != KEMPTY) {
            int id = atomicAdd(&g_hist[g_bi_bkt[i]], 1);
            g_bi_hk[i] = k | ((unsigned long long)id << 40);
            g_bi_kl[id] = k;
            g_bi_nA[id] = 0.0f;
            ((float4*)g_bi_vC)[id] = make_float4(0, 0, 0, 0);
        }
    } else {
        int j = i - BI_CAP;
        if (j < SP_CAP) {
            unsigned long long k = g_sp_hk[j];
            if (k != KEMPTY) {
                int id = atomicAdd(&g_hist[NBKT + g_sp_bkt[j]], 1);
                g_sp_hk[j] = k | ((unsigned long long)id << 40);
                g_sp_kl[id] = k;
                g_sp_nA[id] = 0.0f;
                ((float4*)g_sp_vC)[id] = make_float4(0, 0, 0, 0);
            }
        }
    }
}

__global__ void k_fixoff() {
    cudaGridDependencySynchronize();
    int i = blockIdx.x * blockDim.x + threadIdx.x;
    if (i < BI_MMAX) {
        int slot = __float_as_int(g_bi_ow[i].x);
        g_bi_ow[i].x = __int_as_float((int)(g_bi_hk[slot] >> 40));
    } else {
        int k = i - BI_MMAX;
        if (k < SP_MMAX) {
            int slot = __float_as_int(g_sp_ow[k].x);
            g_sp_ow[k].x = __int_as_float((int)(g_sp_hk[slot] >> 40));
        }
    }
}

template<int D>
DEVF void neigh_one(int i) {
    if (i >= *CNT<D>()) return;
    unsigned long long key = KL<D>()[i];
    int c[D];
#pragma unroll
    for (int j = 0; j < D; j++) c[j] = (int)((key >> (KBITS<D>() * j)) & KMASK<D>()) - KBIAS<D>();
#pragma unroll
    for (int j = 0; j <= D; j++) {
        unsigned long long k1 = 0ull, k2 = 0ull;
#pragma unroll
        for (int t = 0; t < D; t++) {
            int add = (j < D && t == j) ? (D + 1) : 0;
            int c1 = c[t] - 1 + add;
            int c2 = c[t] + 1 - add;
            k1 |= ((unsigned long long)((unsigned)(c1 + KBIAS<D>()) & KMASK<D>())) << (KBITS<D>() * t);
            k2 |= ((unsigned long long)((unsigned)(c2 + KBIAS<D>()) & KMASK<D>())) << (KBITS<D>() * t);
        }
        ((int2*)BNA<D>())[j * MMAXC<D>() + i] = make_int2(find_id<D>(k1), find_id<D>(k2));
    }
}

// both lattices in one launch
__global__ void k_neighAll() {
    cudaGridDependencySynchronize();
    int i = blockIdx.x * blockDim.x + threadIdx.x;
    if (i < BI_MMAX) neigh_one<DBI>(i);
    else { int k = i - BI_MMAX; if (k < SP_MMAX) neigh_one<DSP>(k); }
}

// ---------------- loop kernels (PDL-launched, implicit trigger at completion) ----------------

// initial Q = softmax(logits); splat Q into vC and ones into nA
__global__ void k_initQ(const float* __restrict__ logits) {
    int n = blockIdx.x * blockDim.x + threadIdx.x;
    if (n >= NPIX) { cudaGridDependencySynchronize(); return; }
    float4 lg = ((const float4*)logits)[n];
    cudaGridDependencySynchronize();   // ow/vC/nA ready (fixoff+assign complete)
    float2 bow[DBI + 1], sow[DSP + 1];
#pragma unroll
    for (int m = 0; m <= DBI; m++) bow[m] = g_bi_ow[n * (DBI + 1) + m];
#pragma unroll
    for (int m = 0; m <= DSP; m++) sow[m] = g_sp_ow[n * (DSP + 1) + m];
    float mx = fmaxf(fmaxf(lg.x, lg.y), fmaxf(lg.z, lg.w));
    float e0 = expf(lg.x - mx), e1 = expf(lg.y - mx), e2 = expf(lg.z - mx), e3 = expf(lg.w - mx);
    float inv = 1.0f / (e0 + e1 + e2 + e3);
    float q0 = e0 * inv, q1 = e1 * inv, q2 = e2 * inv, q3 = e3 * inv;
#pragma unroll
    for (int m = 0; m <= DBI; m++) {
        int id = __float_as_int(bow[m].x);
        float w = bow[m].y;
        red4(&g_bi_vC[id * 4], w * q0, w * q1, w * q2, w * q3);
        red1(&g_bi_nA[id], w);
    }
#pragma unroll
    for (int m = 0; m <= DSP; m++) {
        int id = __float_as_int(sow[m].x);
        float w = sow[m].y;
        red4(&g_sp_vC[id * 4], w * q0, w * q1, w * q2, w * q3);
        red1(&g_sp_nA[id], w);
    }
}

// value-blur of a pair (i, i+1); nbp preloaded
template<int D, int C, bool CLR>
DEVF void blur_vals(int i, int cnt, int4 nbp, int inb, int outb) {
    bool two = (i + 1 < cnt);
    {
        const float4* in = (const float4*)VBUF<D>(inb);
        float4* outp = (float4*)VBUF<D>(outb);
        float4 v0 = in[i];
        float4 a0 = make_float4(0, 0, 0, 0), b0 = a0;
        if (nbp.x >= 0) a0 = in[nbp.x];
        if (nbp.y >= 0) b0 = in[nbp.y];
        v0.x += 0.5f * (a0.x + b0.x); v0.y += 0.5f * (a0.y + b0.y);
        v0.z += 0.5f * (a0.z + b0.z); v0.w += 0.5f * (a0.w + b0.w);
        outp[i] = v0;
        if (two) {
            float4 v1 = in[i + 1];
            float4 a1 = make_float4(0, 0, 0, 0), b1 = a1;
            if (nbp.z >= 0) a1 = in[nbp.z];
            if (nbp.w >= 0) b1 = in[nbp.w];
            v1.x += 0.5f * (a1.x + b1.x); v1.y += 0.5f * (a1.y + b1.y);
            v1.z += 0.5f * (a1.z + b1.z); v1.w += 0.5f * (a1.w + b1.w);
            outp[i + 1] = v1;
        }
        if (CLR) {
            float4* cb = (float4*)VBUF<D>(2);
            cb[i] = make_float4(0, 0, 0, 0);
            if (two) cb[i + 1] = make_float4(0, 0, 0, 0);
        }
    }
    if (C == 5) {
        int nin = (inb == 2) ? 0 : inb;
        const float* in = NBUF<D>(nin);
        float* outp = NBUF<D>(outb);
        float s0 = 0.0f;
        if (nbp.x >= 0) s0 += in[nbp.x];
        if (nbp.y >= 0) s0 += in[nbp.y];
        outp[i] = in[i] + 0.5f * s0;
        if (two) {
            float s1 = 0.0f;
            if (nbp.z >= 0) s1 += in[nbp.z];
            if (nbp.w >= 0) s1 += in[nbp.w];
            outp[i + 1] = in[i + 1] + 0.5f * s1;
        }
    }
}

template<int C, bool CLR>
__global__ void k_blur(int axis, int inb, int outb) {
    int t = blockIdx.x * blockDim.x + threadIdx.x;
    // static prologue: counts + neighbor indices (written in setup, constant in loop)
    if (t < BI_PAIRS) {
        int i = 2 * t;
        int cnt = g_bi_cnt;
        if (i >= cnt) { cudaGridDependencySynchronize(); return; }
        int4 nbp = *(const int4*)(((const int2*)g_bi_bn) + axis * BI_MMAX + i);
        cudaGridDependencySynchronize();
        blur_vals<DBI, C, CLR>(i, cnt, nbp, inb, outb);
    } else {
        int k = t - BI_PAIRS;
        if (k >= SP_PAIRS) { cudaGridDependencySynchronize(); return; }
        int i = 2 * k;
        int cnt = g_sp_cnt;
        if (i >= cnt) { cudaGridDependencySynchronize(); return; }
        int4 nbp = *(const int4*)(((const int2*)g_sp_bn) + axis * SP_MMAX + i);
        cudaGridDependencySynchronize();
        blur_vals<DSP, C, CLR>(i, cnt, nbp, inb, outb);
    }
}

// mean-field update. MODE 0 = first (slices norm channel, stores norms),
// 1 = middle, 2 = last (writes output, no splat)
template<int MODE>
__global__ void k_update(const float* __restrict__ logits, float* __restrict__ out) {
    int n = blockIdx.x * blockDim.x + threadIdx.x;
    if (n >= NPIX) { cudaGridDependencySynchronize(); return; }
    // static prologue
    float2 bow[DBI + 1], sow[DSP + 1];
#pragma unroll
    for (int m = 0; m <= DBI; m++) bow[m] = g_bi_ow[n * (DBI + 1) + m];
#pragma unroll
    for (int m = 0; m <= DSP; m++) sow[m] = g_sp_ow[n * (DSP + 1) + m];
    float4 lg = ((const float4*)logits)[n];
    float nb_ = 0, ns_ = 0;
    if (MODE != 0) { nb_ = g_bi_norm[n]; ns_ = g_sp_norm[n]; }
    cudaGridDependencySynchronize();

    const float4* vb = (const float4*)g_bi_vA; // bi after 6 passes (C->B->A->B->A->B->A)
    const float4* vs = (const float4*)g_sp_vB; // sp after 3 passes (C->B->A->B)
    float ab0 = 0, ab1 = 0, ab2 = 0, ab3 = 0, sb = 0;
    float as0 = 0, as1 = 0, as2 = 0, as3 = 0, ss = 0;
#pragma unroll
    for (int m = 0; m <= DBI; m++) {
        int id = __float_as_int(bow[m].x);
        float w = bow[m].y;
        float4 t = vb[id];
        ab0 += w * t.x; ab1 += w * t.y; ab2 += w * t.z; ab3 += w * t.w;
        if (MODE == 0) sb += w * g_bi_nA[id];
    }
#pragma unroll
    for (int m = 0; m <= DSP; m++) {
        int id = __float_as_int(sow[m].x);
        float w = sow[m].y;
        float4 t = vs[id];
        as0 += w * t.x; as1 += w * t.y; as2 += w * t.z; as3 += w * t.w;
        if (MODE == 0) ss += w * g_sp_nB[id];
    }
    if (MODE == 0) {
        nb_ = sb * ALPHA_BI; g_bi_norm[n] = nb_;
        ns_ = ss * ALPHA_SP; g_sp_norm[n] = ns_;
    }
    float fbi = 10.0f * ALPHA_BI / (nb_ + 1e-20f);
    float fsp = 3.0f * ALPHA_SP / (ns_ + 1e-20f);
    float a0 = lg.x + fbi * ab0 + fsp * as0;
    float a1 = lg.y + fbi * ab1 + fsp * as1;
    float a2 = lg.z + fbi * ab2 + fsp * as2;
    float a3 = lg.w + fbi * ab3 + fsp * as3;
    float mx = fmaxf(fmaxf(a0, a1), fmaxf(a2, a3));
    float e0 = expf(a0 - mx), e1 = expf(a1 - mx), e2 = expf(a2 - mx), e3 = expf(a3 - mx);
    float inv = 1.0f / (e0 + e1 + e2 + e3);
    float q0 = e0 * inv, q1 = e1 * inv, q2 = e2 * inv, q3 = e3 * inv;
    if (MODE == 2) {
        ((float4*)out)[n] = make_float4(q0, q1, q2, q3);
    } else {
#pragma unroll
        for (int m = 0; m <= DBI; m++) {
            int id = __float_as_int(bow[m].x);
            float w = bow[m].y;
            red4(&g_bi_vC[id * 4], w * q0, w * q1, w * q2, w * q3);
        }
#pragma unroll
        for (int m = 0; m <= DSP; m++) {
            int id = __float_as_int(sow[m].x);
            float w = sow[m].y;
            red4(&g_sp_vC[id * 4], w * q0, w * q1, w * q2, w * q3);
        }
    }
}

// ---------------- launch ----------------
template<typename K, typename... Args>
static void launch_pdl(unsigned grid, unsigned block, K kernel, Args... args) {
    cudaLaunchConfig_t cfg = {};
    cfg.gridDim = dim3(grid, 1, 1);
    cfg.blockDim = dim3(block, 1, 1);
    cfg.dynamicSmemBytes = 0;
    cfg.stream = 0;
    cudaLaunchAttribute at[1];
    at[0].id = cudaLaunchAttributeProgrammaticStreamSerialization;
    at[0].val.programmaticStreamSerializationAllowed = 1;
    cfg.attrs = at;
    cfg.numAttrs = 1;
    cudaLaunchKernelEx(&cfg, kernel, args...);
}

extern "C" void kernel_launch(void* const* d_in, const int* in_sizes, int n_in,
                              void* d_out, int out_size) {
    (void)in_sizes; (void)n_in; (void)out_size;
    const float* x      = (const float*)d_in[0];
    const float* logits = (const float*)d_in[1];
    float* out = (float*)d_out;

    const int B = 256;
    auto g = [](long n) { return (unsigned)((n + 255) / 256); };
    const unsigned G_BOTH   = g(BI_MMAX + SP_MMAX);
    const unsigned G_CAPS   = g(BI_CAP + SP_CAP);
    const unsigned G_PAIRS  = g(BI_PAIRS + SP_PAIRS);
    const unsigned G_PAIRSB = g(BI_PAIRS);
    const unsigned G_PIX    = g(NPIX);

    // ---- lattice construction (PDL chain) ----
    k_resetAll<<<G_CAPS, B>>>();
    launch_pdl(G_PIX, B, k_build<DBI>, x);
    launch_pdl(G_PIX, B, k_build<DSP>, x);
    launch_pdl(1u, 1024u, k_scan);
    launch_pdl(G_CAPS, B, k_assign);
    launch_pdl(G_BOTH, B, k_fixoff);
    launch_pdl(G_BOTH, B, k_neighAll);

    // ---- init + mean-field iterations (PDL chain; norm fused into iteration 0) ----
    launch_pdl(G_PIX, B, k_initQ, logits);
    for (int it = 0; it < N_ITER; it++) {
        for (int j = 0; j <= DBI; j++) {
            int inb  = (j == 0) ? 2 : (j & 1);
            int outb = (j & 1) ^ 1;
            unsigned grd = (j <= DSP) ? G_PAIRS : G_PAIRSB;
            if (it == 0) {
                if (j == 1) launch_pdl(grd, B, k_blur<5, true>,  j, inb, outb);
                else        launch_pdl(grd, B, k_blur<5, false>, j, inb, outb);
            } else {
                if (j == 1) launch_pdl(grd, B, k_blur<4, true>,  j, inb, outb);
                else        launch_pdl(grd, B, k_blur<4, false>, j, inb, outb);
            }
        }
        if (it == 0)
            launch_pdl(G_PIX, B, k_update<0>, logits, out);
        else if (it == N_ITER - 1)
            launch_pdl(G_PIX, B, k_update<2>, logits, out);
        else
            launch_pdl(G_PIX, B, k_update<1>, logits, out);
    }
}

// round 17
// speedup vs baseline: 1.0290x; 1.0230x over previous
#include <cuda_runtime.h>
#include <math.h>

#define DEVF __device__ __forceinline__

// ---------------- problem constants ----------------
constexpr int HH = 512, WW = 512, NPIX = HH * WW, NC = 4;
constexpr int DBI = 5, DSP = 2;
constexpr int N_ITER = 10;

constexpr int BI_CAP = 1 << 22;
constexpr int SP_CAP = 1 << 19;
constexpr int BI_MMAX = NPIX * (DBI + 1); // 1,572,864
constexpr int SP_MMAX = NPIX * (DSP + 1); //   786,432
constexpr int BI_PAIRS = BI_MMAX / 2;
constexpr int SP_PAIRS = SP_MMAX / 2;
constexpr int NBKT = 4096;               // 64x64 grid of 8x8-pixel tiles
constexpr unsigned long long KEMPTY = ~0ull;
constexpr unsigned long long M40 = (1ull << 40) - 1;
constexpr float ALPHA_BI = 32.0f / 33.0f;
constexpr float ALPHA_SP = 0.8f;

// ---------------- device scratch ----------------
__device__ unsigned long long g_bi_hk[BI_CAP];   // key (40b) | id<<40 after assign
__device__ unsigned long long g_sp_hk[SP_CAP];
__device__ int   g_bi_bkt[BI_CAP];
__device__ int   g_sp_bkt[SP_CAP];
__device__ int   g_hist[2 * NBKT];
__device__ unsigned long long g_bi_kl[BI_MMAX];
__device__ unsigned long long g_sp_kl[SP_MMAX];
// interleaved (id, weight) pairs: .x = bitcast id (slot before fixoff), .y = barycentric w
__device__ __align__(16) float2 g_bi_ow[BI_MMAX];
__device__ __align__(16) float2 g_sp_ow[SP_MMAX];
__device__ __align__(16) int g_bi_bn[(DBI + 1) * BI_MMAX * 2];
__device__ __align__(16) int g_sp_bn[(DSP + 1) * SP_MMAX * 2];
// value buffers: A(0), B(1) ping-pong; C(2) = splat target
__device__ __align__(16) float g_bi_vA[BI_MMAX * NC];
__device__ __align__(16) float g_bi_vB[BI_MMAX * NC];
__device__ __align__(16) float g_bi_vC[BI_MMAX * NC];
__device__ __align__(16) float g_sp_vA[SP_MMAX * NC];
__device__ __align__(16) float g_sp_vB[SP_MMAX * NC];
__device__ __align__(16) float g_sp_vC[SP_MMAX * NC];
__device__ float g_bi_nA[BI_MMAX];
__device__ float g_bi_nB[BI_MMAX];
__device__ float g_sp_nA[SP_MMAX];
__device__ float g_sp_nB[SP_MMAX];
__device__ float g_bi_norm[NPIX];
__device__ float g_sp_norm[NPIX];
__device__ int   g_bi_cnt, g_sp_cnt;

// ---------------- templated accessors ----------------
template<int D> DEVF unsigned long long* HK()  { return D == DBI ? g_bi_hk  : g_sp_hk;  }
template<int D> DEVF int*    BKT() { return D == DBI ? g_bi_bkt : g_sp_bkt; }
template<int D> DEVF unsigned long long* KL()  { return D == DBI ? g_bi_kl  : g_sp_kl;  }
template<int D> DEVF float2* OWA() { return D == DBI ? g_bi_ow  : g_sp_ow;  }
template<int D> DEVF int*    BNA() { return D == DBI ? g_bi_bn  : g_sp_bn;  }
template<int D> DEVF int*    CNT() { return D == DBI ? &g_bi_cnt: &g_sp_cnt;}
template<int D> DEVF int     CAPC(){ return D == DBI ? BI_CAP   : SP_CAP;   }
template<int D> DEVF int     MMAXC(){ return D == DBI ? BI_MMAX : SP_MMAX;  }
template<int D> DEVF int     KBITS(){ return D == DBI ? 8 : 10; }
template<int D> DEVF int     KBIAS(){ return D == DBI ? 128 : 512; }
template<int D> DEVF unsigned KMASK(){ return D == DBI ? 0xFFu : 0x3FFu; }
template<int D> DEVF int     HBASE(){ return D == DBI ? 0 : NBKT; }

template<int D> DEVF float* VBUF(int which) {
    if (D == DBI) return which == 2 ? g_bi_vC : (which ? g_bi_vB : g_bi_vA);
    return which == 2 ? g_sp_vC : (which ? g_sp_vB : g_sp_vA);
}
template<int D> DEVF float* NBUF(int which) {
    return D == DBI ? (which ? g_bi_nB : g_bi_nA) : (which ? g_sp_nB : g_sp_nA);
}

// vectorized float4 reduction (sm_90+)
DEVF void red4(float* p, float a, float b, float c, float d) {
    asm volatile("{ .reg .u64 pg; cvta.to.global.u64 pg, %0; "
                 "red.global.add.v4.f32 [pg], {%1,%2,%3,%4}; }"
                 :: "l"(p), "f"(a), "f"(b), "f"(c), "f"(d) : "memory");
}
DEVF void red1(float* p, float a) {
    asm volatile("{ .reg .u64 pg; cvta.to.global.u64 pg, %0; "
                 "red.global.add.f32 [pg], %1; }"
                 :: "l"(p), "f"(a) : "memory");
}

// ---------------- hash ----------------
DEVF unsigned long long hmix(unsigned long long x) {
    x += 0x9E3779B97F4A7C15ull;
    x = (x ^ (x >> 30)) * 0xBF58476D1CE4E5B9ull;
    x = (x ^ (x >> 27)) * 0x94D049BB133111EBull;
    return x ^ (x >> 31);
}

template<int D>
DEVF int insert_slot(unsigned long long key, int bkt) {
    const unsigned mask = (unsigned)(CAPC<D>() - 1);
    unsigned long long* hk = HK<D>();
    unsigned h = (unsigned)hmix(key) & mask;
    for (;;) {
        unsigned long long prev = atomicCAS(&hk[h], KEMPTY, key);
        if (prev == KEMPTY) {
            BKT<D>()[h] = bkt;
            atomicAdd(&g_hist[HBASE<D>() + bkt], 1);
            return (int)h;
        }
        if (prev == key) return (int)h;
        h = (h + 1) & mask;
    }
}

template<int D>
DEVF int find_id(unsigned long long key) {
    const unsigned mask = (unsigned)(CAPC<D>() - 1);
    const unsigned long long* hk = HK<D>();
    unsigned h = (unsigned)hmix(key) & mask;
    for (;;) {
        unsigned long long v = hk[h];
        if (v == KEMPTY) return -1;
        if ((v & M40) == key) return (int)(v >> 40);
        h = (h + 1) & mask;
    }
}

// ---------------- setup kernels ----------------
// reset both hash tables + histograms in one launch
__global__ void k_resetAll() {
    int i = blockIdx.x * blockDim.x + threadIdx.x;
    if (i < BI_CAP) {
        g_bi_hk[i] = KEMPTY;
        if (i < 2 * NBKT) g_hist[i] = 0;
    } else {
        int k = i - BI_CAP;
        if (k < SP_CAP) g_sp_hk[k] = KEMPTY;
    }
}

template<int D>
__global__ void k_build(const float* __restrict__ x) {
    int n = blockIdx.x * blockDim.x + threadIdx.x;
    if (n >= NPIX) { cudaGridDependencySynchronize(); return; }
    int py = n / WW, px = n - py * WW;
    int bkt = ((py >> 3) << 6) | (px >> 3);   // 8x8 pixel tile id (64x64 grid)

    float fs[D];
    const double inv_std = sqrt(2.0 / 3.0) * (D + 1);
#pragma unroll
    for (int j = 0; j < D; j++) {
        float f;
        if (D == DBI) {
            if (j == 0)      f = __fdiv_rn((float)px, 80.0f);
            else if (j == 1) f = __fdiv_rn((float)py, 80.0f);
            else             f = __fdiv_rn(x[n * 7 + (6 - j)], 0.0625f);
        } else {
            f = __fdiv_rn((float)(j == 0 ? px : py), 3.0f);
        }
        float sc = (float)(1.0 / sqrt((j + 2.0) * (j + 1.0)) * inv_std);
        fs[j] = __fmul_rn(f, sc);
    }

    float elev[D + 1];
#pragma unroll
    for (int r = 0; r <= D; r++) {
        float s = 0.0f;
#pragma unroll
        for (int j = 0; j < D; j++) {
            float e = (r == 0) ? 1.0f : ((j == r - 1) ? -(float)r : (j >= r ? 1.0f : 0.0f));
            s = __fadd_rn(s, __fmul_rn(e, fs[j]));
        }
        elev[r] = s;
    }

    const float downf = __fdiv_rn(1.0f, (float)(D + 1));
    const float upf = (float)(D + 1);

    float rem0[D + 1], diff[D + 1];
    int   rnk[D + 1];
#pragma unroll
    for (int k = 0; k <= D; k++) {
        float v   = __fmul_rn(elev[k], downf);
        float upr = __fmul_rn(ceilf(v),  upf);
        float dnr = __fmul_rn(floorf(v), upf);
        rem0[k] = (__fsub_rn(upr, elev[k]) < __fsub_rn(elev[k], dnr)) ? upr : dnr;
    }
    float ssum = 0.0f;
#pragma unroll
    for (int k = 0; k <= D; k++) ssum = __fadd_rn(ssum, rem0[k]);
    int s = (int)__fmul_rn(ssum, downf);

#pragma unroll
    for (int k = 0; k <= D; k++) diff[k] = __fsub_rn(elev[k], rem0[k]);
#pragma unroll
    for (int k = 0; k <= D; k++) {
        int r = s;
#pragma unroll
        for (int j = 0; j <= D; j++) {
            if (j > k)      r += (diff[k] <  diff[j]);
            else if (j < k) r += (diff[j] >= diff[k]);
        }
        rnk[k] = r;
    }
#pragma unroll
    for (int k = 0; k <= D; k++) {
        if (rnk[k] < 0)      { rnk[k] += D + 1; rem0[k] = __fadd_rn(rem0[k], upf); }
        else if (rnk[k] > D) { rnk[k] -= D + 1; rem0[k] = __fsub_rn(rem0[k], upf); }
    }

    float b[D + 2];
#pragma unroll
    for (int k = 0; k < D + 2; k++) b[k] = 0.0f;
#pragma unroll
    for (int k = 0; k <= D; k++) {
        float vs = __fmul_rn(__fsub_rn(elev[k], rem0[k]), downf);
        int idx = D - rnk[k];
        b[idx]     = __fadd_rn(b[idx], vs);
        b[idx + 1] = __fsub_rn(b[idx + 1], vs);
    }
    b[0] = __fadd_rn(b[0], __fadd_rn(1.0f, b[D + 1]));

    int remi[D + 1];
#pragma unroll
    for (int k = 0; k <= D; k++) remi[k] = (int)rem0[k];

    // precompute all keys before touching the hash
    unsigned long long keys[D + 1];
#pragma unroll
    for (int m = 0; m <= D; m++) {
        unsigned long long key = 0ull;
#pragma unroll
        for (int j = 0; j < D; j++) {
            int r  = rnk[j];
            int cm = (r < D + 1 - m) ? m : m - (D + 1);
            int c  = remi[j] + cm;
            key |= ((unsigned long long)((unsigned)(c + KBIAS<D>()) & KMASK<D>())) << (KBITS<D>() * j);
        }
        keys[m] = key;
    }
    // wait for reset to finish before hash inserts
    cudaGridDependencySynchronize();
#pragma unroll
    for (int m = 0; m <= D; m++) {
        int slot = insert_slot<D>(keys[m], bkt);
        OWA<D>()[n * (D + 1) + m] = make_float2(__int_as_float(slot), b[m]);
    }
}

// exclusive scan of both 4096-entry histograms; warp-shuffle hierarchical scan
__global__ void k_scan() {
    cudaGridDependencySynchronize();
    __shared__ int warpsum[32];
    int t = threadIdx.x;
    int lane = t & 31, wid = t >> 5;
#pragma unroll
    for (int half = 0; half < 2; half++) {
        int base = half * NBKT + t * 4;
        int v0 = g_hist[base + 0], v1 = g_hist[base + 1];
        int v2 = g_hist[base + 2], v3 = g_hist[base + 3];
        int lsum = v0 + v1 + v2 + v3;
        // warp-inclusive scan of per-thread sums
        int inc = lsum;
#pragma unroll
        for (int o = 1; o < 32; o <<= 1) {
            int u = __shfl_up_sync(0xFFFFFFFFu, inc, o);
            if (lane >= o) inc += u;
        }
        if (lane == 31) warpsum[wid] = inc;
        __syncthreads();
        if (wid == 0) {
            int ws = warpsum[lane];
#pragma unroll
            for (int o = 1; o < 32; o <<= 1) {
                int u = __shfl_up_sync(0xFFFFFFFFu, ws, o);
                if (lane >= o) ws += u;
            }
            warpsum[lane] = ws;
        }
        __syncthreads();
        int run = inc - lsum + (wid > 0 ? warpsum[wid - 1] : 0);
        g_hist[base + 0] = run;          run += v0;
        g_hist[base + 1] = run;          run += v1;
        g_hist[base + 2] = run;          run += v2;
        g_hist[base + 3] = run;
        if (t == 0) {
            if (half == 0) g_bi_cnt = warpsum[31];
            else           g_sp_cnt = warpsum[31];
        }
        __syncthreads();   // protect warpsum reuse in next half
    }
}

__global__ void k_assign() {
    cudaGridDependencySynchronize();
    int i = blockIdx.x * blockDim.x + threadIdx.x;
    if (i < BI_CAP) {
        unsigned long long k = g_bi_hk[i];
        if (k != KEMPTY) {
            int id = atomicAdd(&g_hist[g_bi_bkt[i]], 1);
            g_bi_hk[i] = k | ((unsigned long long)id << 40);
            g_bi_kl[id] = k;
            g_bi_nA[id] = 0.0f;
            ((float4*)g_bi_vC)[id] = make_float4(0, 0, 0, 0);
        }
    } else {
        int j = i - BI_CAP;
        if (j < SP_CAP) {
            unsigned long long k = g_sp_hk[j];
            if (k != KEMPTY) {
                int id = atomicAdd(&g_hist[NBKT + g_sp_bkt[j]], 1);
                g_sp_hk[j] = k | ((unsigned long long)id << 40);
                g_sp_kl[id] = k;
                g_sp_nA[id] = 0.0f;
                ((float4*)g_sp_vC)[id] = make_float4(0, 0, 0, 0);
            }
        }
    }
}

__global__ void k_fixoff() {
    cudaGridDependencySynchronize();
    int i = blockIdx.x * blockDim.x + threadIdx.x;
    if (i < BI_MMAX) {
        int slot = __float_as_int(g_bi_ow[i].x);
        g_bi_ow[i].x = __int_as_float((int)(g_bi_hk[slot] >> 40));
    } else {
        int k = i - BI_MMAX;
        if (k < SP_MMAX) {
            int slot = __float_as_int(g_sp_ow[k].x);
            g_sp_ow[k].x = __int_as_float((int)(g_sp_hk[slot] >> 40));
        }
    }
}

template<int D>
DEVF void neigh_one(int i) {
    if (i >= *CNT<D>()) return;
    unsigned long long key = KL<D>()[i];
    int c[D];
#pragma unroll
    for (int j = 0; j < D; j++) c[j] = (int)((key >> (KBITS<D>() * j)) & KMASK<D>()) - KBIAS<D>();
#pragma unroll
    for (int j = 0; j <= D; j++) {
        unsigned long long k1 = 0ull, k2 = 0ull;
#pragma unroll
        for (int t = 0; t < D; t++) {
            int add = (j < D && t == j) ? (D + 1) : 0;
            int c1 = c[t] - 1 + add;
            int c2 = c[t] + 1 - add;
            k1 |= ((unsigned long long)((unsigned)(c1 + KBIAS<D>()) & KMASK<D>())) << (KBITS<D>() * t);
            k2 |= ((unsigned long long)((unsigned)(c2 + KBIAS<D>()) & KMASK<D>())) << (KBITS<D>() * t);
        }
        ((int2*)BNA<D>())[j * MMAXC<D>() + i] = make_int2(find_id<D>(k1), find_id<D>(k2));
    }
}

// both lattices in one launch
__global__ void k_neighAll() {
    cudaGridDependencySynchronize();
    int i = blockIdx.x * blockDim.x + threadIdx.x;
    if (i < BI_MMAX) neigh_one<DBI>(i);
    else { int k = i - BI_MMAX; if (k < SP_MMAX) neigh_one<DSP>(k); }
}

// ---------------- loop kernels (PDL-launched, implicit trigger at completion) ----------------

// initial Q = softmax(logits); splat Q into vC and ones into nA
__global__ void k_initQ(const float* __restrict__ logits) {
    int n = blockIdx.x * blockDim.x + threadIdx.x;
    if (n >= NPIX) { cudaGridDependencySynchronize(); return; }
    float4 lg = ((const float4*)logits)[n];
    cudaGridDependencySynchronize();   // ow/vC/nA ready (fixoff+assign complete)
    float2 bow[DBI + 1], sow[DSP + 1];
#pragma unroll
    for (int m = 0; m <= DBI; m++) bow[m] = g_bi_ow[n * (DBI + 1) + m];
#pragma unroll
    for (int m = 0; m <= DSP; m++) sow[m] = g_sp_ow[n * (DSP + 1) + m];
    float mx = fmaxf(fmaxf(lg.x, lg.y), fmaxf(lg.z, lg.w));
    float e0 = expf(lg.x - mx), e1 = expf(lg.y - mx), e2 = expf(lg.z - mx), e3 = expf(lg.w - mx);
    float inv = 1.0f / (e0 + e1 + e2 + e3);
    float q0 = e0 * inv, q1 = e1 * inv, q2 = e2 * inv, q3 = e3 * inv;
#pragma unroll
    for (int m = 0; m <= DBI; m++) {
        int id = __float_as_int(bow[m].x);
        float w = bow[m].y;
        red4(&g_bi_vC[id * 4], w * q0, w * q1, w * q2, w * q3);
        red1(&g_bi_nA[id], w);
    }
#pragma unroll
    for (int m = 0; m <= DSP; m++) {
        int id = __float_as_int(sow[m].x);
        float w = sow[m].y;
        red4(&g_sp_vC[id * 4], w * q0, w * q1, w * q2, w * q3);
        red1(&g_sp_nA[id], w);
    }
}

// value-blur of a pair (i, i+1); nbp preloaded
template<int D, int C, bool CLR>
DEVF void blur_vals(int i, int cnt, int4 nbp, int inb, int outb) {
    bool two = (i + 1 < cnt);
    {
        const float4* in = (const float4*)VBUF<D>(inb);
        float4* outp = (float4*)VBUF<D>(outb);
        float4 v0 = in[i];
        float4 a0 = make_float4(0, 0, 0, 0), b0 = a0;
        if (nbp.x >= 0) a0 = in[nbp.x];
        if (nbp.y >= 0) b0 = in[nbp.y];
        v0.x += 0.5f * (a0.x + b0.x); v0.y += 0.5f * (a0.y + b0.y);
        v0.z += 0.5f * (a0.z + b0.z); v0.w += 0.5f * (a0.w + b0.w);
        outp[i] = v0;
        if (two) {
            float4 v1 = in[i + 1];
            float4 a1 = make_float4(0, 0, 0, 0), b1 = a1;
            if (nbp.z >= 0) a1 = in[nbp.z];
            if (nbp.w >= 0) b1 = in[nbp.w];
            v1.x += 0.5f * (a1.x + b1.x); v1.y += 0.5f * (a1.y + b1.y);
            v1.z += 0.5f * (a1.z + b1.z); v1.w += 0.5f * (a1.w + b1.w);
            outp[i + 1] = v1;
        }
        if (CLR) {
            float4* cb = (float4*)VBUF<D>(2);
            cb[i] = make_float4(0, 0, 0, 0);
            if (two) cb[i + 1] = make_float4(0, 0, 0, 0);
        }
    }
    if (C == 5) {
        int nin = (inb == 2) ? 0 : inb;
        const float* in = NBUF<D>(nin);
        float* outp = NBUF<D>(outb);
        float s0 = 0.0f;
        if (nbp.x >= 0) s0 += in[nbp.x];
        if (nbp.y >= 0) s0 += in[nbp.y];
        outp[i] = in[i] + 0.5f * s0;
        if (two) {
            float s1 = 0.0f;
            if (nbp.z >= 0) s1 += in[nbp.z];
            if (nbp.w >= 0) s1 += in[nbp.w];
            outp[i + 1] = in[i + 1] + 0.5f * s1;
        }
    }
}

template<int C, bool CLR>
__global__ void k_blur(int axis, int inb, int outb) {
    int t = blockIdx.x * blockDim.x + threadIdx.x;
    // static prologue: counts + neighbor indices (written in setup, constant in loop)
    if (t < BI_PAIRS) {
        int i = 2 * t;
        int cnt = g_bi_cnt;
        if (i >= cnt) { cudaGridDependencySynchronize(); return; }
        int4 nbp = *(const int4*)(((const int2*)g_bi_bn) + axis * BI_MMAX + i);
        cudaGridDependencySynchronize();
        blur_vals<DBI, C, CLR>(i, cnt, nbp, inb, outb);
    } else {
        int k = t - BI_PAIRS;
        if (k >= SP_PAIRS) { cudaGridDependencySynchronize(); return; }
        int i = 2 * k;
        int cnt = g_sp_cnt;
        if (i >= cnt) { cudaGridDependencySynchronize(); return; }
        int4 nbp = *(const int4*)(((const int2*)g_sp_bn) + axis * SP_MMAX + i);
        cudaGridDependencySynchronize();
        blur_vals<DSP, C, CLR>(i, cnt, nbp, inb, outb);
    }
}

// mean-field update. MODE 0 = first (slices norm channel, stores norms),
// 1 = middle, 2 = last (writes output, no splat)
template<int MODE>
__global__ void k_update(const float* __restrict__ logits, float* __restrict__ out) {
    int n = blockIdx.x * blockDim.x + threadIdx.x;
    if (n >= NPIX) { cudaGridDependencySynchronize(); return; }
    // static prologue
    float2 bow[DBI + 1], sow[DSP + 1];
#pragma unroll
    for (int m = 0; m <= DBI; m++) bow[m] = g_bi_ow[n * (DBI + 1) + m];
#pragma unroll
    for (int m = 0; m <= DSP; m++) sow[m] = g_sp_ow[n * (DSP + 1) + m];
    float4 lg = ((const float4*)logits)[n];
    float nb_ = 0, ns_ = 0;
    if (MODE != 0) { nb_ = g_bi_norm[n]; ns_ = g_sp_norm[n]; }
    cudaGridDependencySynchronize();

    const float4* vb = (const float4*)g_bi_vA; // bi after 6 passes (C->B->A->B->A->B->A)
    const float4* vs = (const float4*)g_sp_vB; // sp after 3 passes (C->B->A->B)
    float ab0 = 0, ab1 = 0, ab2 = 0, ab3 = 0, sb = 0;
    float as0 = 0, as1 = 0, as2 = 0, as3 = 0, ss = 0;
#pragma unroll
    for (int m = 0; m <= DBI; m++) {
        int id = __float_as_int(bow[m].x);
        float w = bow[m].y;
        float4 t = vb[id];
        ab0 += w * t.x; ab1 += w * t.y; ab2 += w * t.z; ab3 += w * t.w;
        if (MODE == 0) sb += w * g_bi_nA[id];
    }
#pragma unroll
    for (int m = 0; m <= DSP; m++) {
        int id = __float_as_int(sow[m].x);
        float w = sow[m].y;
        float4 t = vs[id];
        as0 += w * t.x; as1 += w * t.y; as2 += w * t.z; as3 += w * t.w;
        if (MODE == 0) ss += w * g_sp_nB[id];
    }
    if (MODE == 0) {
        nb_ = sb * ALPHA_BI; g_bi_norm[n] = nb_;
        ns_ = ss * ALPHA_SP; g_sp_norm[n] = ns_;
    }
    float fbi = 10.0f * ALPHA_BI / (nb_ + 1e-20f);
    float fsp = 3.0f * ALPHA_SP / (ns_ + 1e-20f);
    float a0 = lg.x + fbi * ab0 + fsp * as0;
    float a1 = lg.y + fbi * ab1 + fsp * as1;
    float a2 = lg.z + fbi * ab2 + fsp * as2;
    float a3 = lg.w + fbi * ab3 + fsp * as3;
    float mx = fmaxf(fmaxf(a0, a1), fmaxf(a2, a3));
    float e0 = expf(a0 - mx), e1 = expf(a1 - mx), e2 = expf(a2 - mx), e3 = expf(a3 - mx);
    float inv = 1.0f / (e0 + e1 + e2 + e3);
    float q0 = e0 * inv, q1 = e1 * inv, q2 = e2 * inv, q3 = e3 * inv;
    if (MODE == 2) {
        ((float4*)out)[n] = make_float4(q0, q1, q2, q3);
    } else {
#pragma unroll
        for (int m = 0; m <= DBI; m++) {
            int id = __float_as_int(bow[m].x);
            float w = bow[m].y;
            red4(&g_bi_vC[id * 4], w * q0, w * q1, w * q2, w * q3);
        }
#pragma unroll
        for (int m = 0; m <= DSP; m++) {
            int id = __float_as_int(sow[m].x);
            float w = sow[m].y;
            red4(&g_sp_vC[id * 4], w * q0, w * q1, w * q2, w * q3);
        }
    }
}

// ---------------- launch ----------------
template<typename K, typename... Args>
static void launch_pdl(unsigned grid, unsigned block, K kernel, Args... args) {
    cudaLaunchConfig_t cfg = {};
    cfg.gridDim = dim3(grid, 1, 1);
    cfg.blockDim = dim3(block, 1, 1);
    cfg.dynamicSmemBytes = 0;
    cfg.stream = 0;
    cudaLaunchAttribute at[1];
    at[0].id = cudaLaunchAttributeProgrammaticStreamSerialization;
    at[0].val.programmaticStreamSerializationAllowed = 1;
    cfg.attrs = at;
    cfg.numAttrs = 1;
    cudaLaunchKernelEx(&cfg, kernel, args...);
}

extern "C" void kernel_launch(void* const* d_in, const int* in_sizes, int n_in,
                              void* d_out, int out_size) {
    (void)in_sizes; (void)n_in; (void)out_size;
    const float* x      = (const float*)d_in[0];
    const float* logits = (const float*)d_in[1];
    float* out = (float*)d_out;

    const int B = 256;
    auto g = [](long n) { return (unsigned)((n + 255) / 256); };
    const unsigned G_BOTH   = g(BI_MMAX + SP_MMAX);
    const unsigned G_CAPS   = g(BI_CAP + SP_CAP);
    const unsigned G_PAIRS  = g(BI_PAIRS + SP_PAIRS);
    const unsigned G_PAIRSB = g(BI_PAIRS);
    const unsigned G_PIX    = g(NPIX);

    // ---- lattice construction (PDL chain) ----
    k_resetAll<<<G_CAPS, B>>>();
    launch_pdl(G_PIX, B, k_build<DBI>, x);
    launch_pdl(G_PIX, B, k_build<DSP>, x);
    launch_pdl(1u, 1024u, k_scan);
    launch_pdl(G_CAPS, B, k_assign);
    launch_pdl(G_BOTH, B, k_fixoff);
    launch_pdl(G_BOTH, B, k_neighAll);

    // ---- init + mean-field iterations (PDL chain; norm fused into iteration 0) ----
    launch_pdl(G_PIX, B, k_initQ, logits);
    for (int it = 0; it < N_ITER; it++) {
        for (int j = 0; j <= DBI; j++) {
            int inb  = (j == 0) ? 2 : (j & 1);
            int outb = (j & 1) ^ 1;
            unsigned grd = (j <= DSP) ? G_PAIRS : G_PAIRSB;
            if (it == 0) {
                if (j == 1) launch_pdl(grd, B, k_blur<5, true>,  j, inb, outb);
                else        launch_pdl(grd, B, k_blur<5, false>, j, inb, outb);
            } else {
                if (j == 1) launch_pdl(grd, B, k_blur<4, true>,  j, inb, outb);
                else        launch_pdl(grd, B, k_blur<4, false>, j, inb, outb);
            }
        }
        if (it == 0)
            launch_pdl(G_PIX, B, k_update<0>, logits, out);
        else if (it == N_ITER - 1)
            launch_pdl(G_PIX, B, k_update<2>, logits, out);
        else
            launch_pdl(G_PIX, B, k_update<1>, logits, out);
    }
}